// round 13
// baseline (speedup 1.0000x reference)
#include <cuda_runtime.h>
#include <cstdint>

#define T_LEN 4096
#define NB    128
#define G3    180   // 3*H
#define HS    60

typedef unsigned long long ull;

// packed f32x2 helpers (sm_100a)
#define FMA2(d, a, b, c) asm("fma.rn.f32x2 %0, %1, %2, %3;" : "=l"(d) : "l"(a), "l"(b), "l"(c))
#define ADD2(d, a, b)    asm("add.rn.f32x2 %0, %1, %2;"    : "=l"(d) : "l"(a), "l"(b))
__device__ __forceinline__ ull pack2(float x, float y) {
    ull r; asm("mov.b64 %0, {%1,%2};" : "=l"(r) : "f"(x), "f"(y)); return r;
}
__device__ __forceinline__ void unpack2(float& lo, float& hi, ull v) {
    asm("mov.b64 {%0,%1}, %2;" : "=f"(lo), "=f"(hi) : "l"(v));
}
__device__ __forceinline__ float hsum2(ull a, ull b) {
    ull s; ADD2(s, a, b);
    float lo, hi; unpack2(lo, hi, s);
    return lo + hi;
}

// ---------------- scratch (static device globals; no allocations) ----------------
// gi layout: [d][b][t][g], padded both ends so deep prefetch over/underruns stay in-bounds.
__device__ __align__(16) float g_gi_raw[(size_t)2 * NB * T_LEN * G3 + 4096];
#define GI_BASE (g_gi_raw + 2048)
__device__ float g_y [(size_t)T_LEN * NB * 120];      // [t][b][2H]
__device__ float g_logits[(size_t)NB * 5 * T_LEN];    // [b][c][t]
__device__ float g_msum[NB * 5];

// HW tanh (MUFU.TANH, sm_75+): ~2e-5 abs err, single-op
__device__ __forceinline__ float tanh_f(float x) {
    float y; asm("tanh.approx.f32 %0, %1;" : "=f"(y) : "f"(x)); return y;
}
__device__ __forceinline__ float sigmoid_f(float x) {
    return fmaf(0.5f, tanh_f(0.5f * x), 0.5f);
}

// ---------------- input projection: 512 threads, t-pairs in f32x2 lanes ----------------
// gi[d][b][t][g] = b_ih[d][g] + sum_i in[t][b][i]*W[d][g][i]
// Thread map: gq = tid%60 (gates 3gq..3gq+2), tg = tid/60 (16 t's each); 480 active.
template <int K, bool L0>
__global__ __launch_bounds__(512, 1)
void proj_kernel(const float* __restrict__ in,
                 const float* __restrict__ w_ih,
                 const float* __restrict__ b_ih)
{
    constexpr int TT  = 128;       // t-tile
    constexpr int TTP = 132;       // padded t stride (16B-aligned rows)
    constexpr int GP  = 194;       // padded g stride

    extern __shared__ float sm[];
    float* s_in = sm;              // [K][TTP]
    float* s_w  = sm + K * TTP;    // [K][GP]

    const int tb0 = blockIdx.x * TT;
    const int b   = blockIdx.y;
    const int d   = blockIdx.z;
    const int tid = threadIdx.x;

    if (L0) {
        // x: (B, K, T) -> s_in[i][t]   (coalesced over t)
        for (int idx = tid; idx < K * TT; idx += 512) {
            int i = idx / TT, t = idx % TT;
            s_in[i * TTP + t] = in[((size_t)b * K + i) * T_LEN + tb0 + t];
        }
    } else {
        // y: (T, B, 120) -> s_in[i][t] (coalesced over i)
        for (int idx = tid; idx < K * TT; idx += 512) {
            int t = idx / K, i = idx % K;
            s_in[i * TTP + t] = g_y[((size_t)(tb0 + t) * NB + b) * K + i];
        }
    }
    // weights: w_ih[d][g][k] -> s_w[k][g]
    const float* wd = w_ih + (size_t)d * G3 * K;
    for (int idx = tid; idx < G3 * K; idx += 512) {
        int g = idx / K, k = idx % K;
        s_w[k * GP + g] = wd[idx];
    }
    __syncthreads();

    const int gq = tid % 60;   // gate triple: gates 3gq, 3gq+1, 3gq+2
    const int tg = tid / 60;   // t-group: t in [tg*16, tg*16+16)
    const bool active = tid < 480;

    if (active) {
        ull acc[8][3];
#pragma unroll
        for (int i = 0; i < 8; i++)
#pragma unroll
            for (int j = 0; j < 3; j++) acc[i][j] = 0ull;

#pragma unroll 2
        for (int k = 0; k < K; k++) {
            const ulonglong2* ap2 = (const ulonglong2*)(s_in + k * TTP + tg * 16);
            ulonglong2 A0 = ap2[0], A1 = ap2[1], A2 = ap2[2], A3 = ap2[3];
            ull a[8] = {A0.x, A0.y, A1.x, A1.y, A2.x, A2.y, A3.x, A3.y};
            const float* wk = s_w + k * GP + 3 * gq;
            float w0f = wk[0], w1f = wk[1], w2f = wk[2];
            ull w0 = pack2(w0f, w0f), w1 = pack2(w1f, w1f), w2 = pack2(w2f, w2f);
#pragma unroll
            for (int i = 0; i < 8; i++) {
                FMA2(acc[i][0], a[i], w0, acc[i][0]);
                FMA2(acc[i][1], a[i], w1, acc[i][1]);
                FMA2(acc[i][2], a[i], w2, acc[i][2]);
            }
        }

        float* gout = GI_BASE + (((size_t)d * NB + b) * T_LEN) * G3;
        const int t0 = tb0 + tg * 16;
#pragma unroll
        for (int j = 0; j < 3; j++) {
            const int g = 3 * gq + j;
            const float bb = __ldg(b_ih + d * G3 + g);
#pragma unroll
            for (int i = 0; i < 8; i++) {
                float lo, hi; unpack2(lo, hi, acc[i][j]);
                gout[(size_t)(t0 + 2 * i)     * G3 + g] = lo + bb;
                gout[(size_t)(t0 + 2 * i + 1) * G3 + g] = hi + bb;
            }
        }
    }
}

// ---------------- GRU scan: one CTA per batch, BOTH directions (256 threads).
// warps 0-3 = fwd (d=0), warps 4-7 = bwd (d=1); per-direction named barriers.
// Statically-indexed depth-8 prefetch ring: slot u consumed at step s, reloaded for s+8.
__global__ __launch_bounds__(256)
void scan_kernel(const float* __restrict__ w_hh,
                 const float* __restrict__ b_hh)
{
    const int b    = blockIdx.x;
    const int tid  = threadIdx.x;
    const int d    = tid >> 7;          // 0 or 1 (warp-aligned groups)
    const int lt   = tid & 127;         // lane-in-direction
    const int j    = lt >> 1;
    const int half = lt & 1;
    const int jeff = (j < HS) ? j : (HS - 1);   // keep lanes converged

    __shared__ __align__(16) float s_h[2][2][64];   // [dir][buf][h]

    // half of each gate-row of W_hh -> registers (packed pairs)
    ull wr[15], wz[15], wn[15];
    {
        const ull* pr = (const ull*)(w_hh + ((size_t)d * G3 + jeff) * HS + half * 30);
        const ull* pz = (const ull*)(w_hh + ((size_t)d * G3 + jeff + HS) * HS + half * 30);
        const ull* pn = (const ull*)(w_hh + ((size_t)d * G3 + jeff + 2 * HS) * HS + half * 30);
#pragma unroll
        for (int k = 0; k < 15; k++) { wr[k] = pr[k]; wz[k] = pz[k]; wn[k] = pn[k]; }
    }
    float br = 0.f, bz = 0.f, bn = 0.f;
    if (half == 0) {
        br = b_hh[d * G3 + jeff];
        bz = b_hh[d * G3 + jeff + HS];
        bn = b_hh[d * G3 + jeff + 2 * HS];
    }
    if (lt < 64) { s_h[d][0][lt] = 0.f; s_h[d][1][lt] = 0.f; }
    __syncthreads();

    const long long dstep = (d ? -(long long)G3 : (long long)G3);
    const long long ystep = (d ? -(long long)(NB * 120) : (long long)(NB * 120));
    const size_t tstart = d ? (size_t)(T_LEN - 1) : 0;

    const float* q = GI_BASE + (((size_t)d * NB + b) * T_LEN + tstart) * G3 + jeff;
    float* yp = g_y + tstart * (NB * 120) + (size_t)b * 120 + d * HS + jeff;

    // depth-8 prefetch ring, statically indexed (no shifts; LDG consumed 8 steps later).
    // Over/underruns land in adjacent gi regions or the array pad -> always in-bounds.
    float fr[8], fz[8], fn[8];
#pragma unroll
    for (int i = 0; i < 8; i++) {
        fr[i] = fz[i] = fn[i] = 0.f;
        if (half == 0) { fr[i] = __ldg(q); fz[i] = __ldg(q + HS); fn[i] = __ldg(q + 2 * HS); }
        q += dstep;
    }

    const int bar_id = 1 + d;   // named barrier per direction (warps aligned)

    int cb = 0;
    for (int s0 = 0; s0 < T_LEN; s0 += 8) {
#pragma unroll
        for (int u = 0; u < 8; u++) {
            float gir = fr[u], giz = fz[u], gin = fn[u];
            if (half == 0) {   // reload slot u for step s0+u+8 (unconditional; pad covers edges)
                fr[u] = __ldg(q); fz[u] = __ldg(q + HS); fn[u] = __ldg(q + 2 * HS);
            }
            q += dstep;

            // partial dots over this half's 30 h-elements
            ull a_r0 = 0, a_r1 = 0, a_z0 = 0, a_z1 = 0, a_n0 = 0, a_n1 = 0;
            const ull* hv = (const ull*)&s_h[d][cb][half * 30];
#pragma unroll
            for (int k = 0; k < 15; k++) {
                ull hk = hv[k];
                if (k & 1) {
                    FMA2(a_r1, wr[k], hk, a_r1);
                    FMA2(a_z1, wz[k], hk, a_z1);
                    FMA2(a_n1, wn[k], hk, a_n1);
                } else {
                    FMA2(a_r0, wr[k], hk, a_r0);
                    FMA2(a_z0, wz[k], hk, a_z0);
                    FMA2(a_n0, wn[k], hk, a_n0);
                }
            }
            float ghr = hsum2(a_r0, a_r1);
            float ghz = hsum2(a_z0, a_z1);
            float ghn = hsum2(a_n0, a_n1);
            ghr += __shfl_xor_sync(0xffffffffu, ghr, 1);
            ghz += __shfl_xor_sync(0xffffffffu, ghz, 1);
            ghn += __shfl_xor_sync(0xffffffffu, ghn, 1);

            if (half == 0 && j < HS) {
                float r = sigmoid_f(gir + (br + ghr));
                float z = sigmoid_f(giz + (bz + ghz));
                float n = tanh_f(fmaf(r, bn + ghn, gin));
                float h_old = s_h[d][cb][j];
                float hnew = fmaf(z, h_old - n, n);     // (1-z)*n + z*h
                s_h[d][cb ^ 1][j] = hnew;
                *yp = hnew;
            }
            yp += ystep;
            asm volatile("bar.sync %0, 128;" :: "r"(bar_id) : "memory");
            cb ^= 1;
        }
    }
}

// ---------------- frame head: (T,B,120) -> logits (b,c,t). One CTA per t.
// 256 threads: b = tid&127, hb = tid>>7; each half computes half the outputs per stage.
__global__ __launch_bounds__(256)
void head_kernel(const float* __restrict__ fw1, const float* __restrict__ fb1,
                 const float* __restrict__ fw2, const float* __restrict__ fb2,
                 const float* __restrict__ fw3, const float* __restrict__ fb3)
{
    extern __shared__ float sm[];
    float* s_x  = sm;                    // [128][121]
    float* s_w1 = s_x  + 128 * 121;      // [60][120]
    float* s_h1 = s_w1 + 60 * 120;       // [128][61]
    float* s_w2 = s_h1 + 128 * 61;       // [40][60]
    float* s_h2 = s_w2 + 40 * 60;        // [128][41]
    float* s_w3 = s_h2 + 128 * 41;       // [5][40]

    const int t   = blockIdx.x;
    const int tid = threadIdx.x;

    for (int idx = tid; idx < 128 * 120; idx += 256) {
        int r = idx / 120, i = idx % 120;
        s_x[r * 121 + i] = g_y[((size_t)t * NB + r) * 120 + i];
    }
    for (int idx = tid; idx < 60 * 120; idx += 256) s_w1[idx] = fw1[idx];
    for (int idx = tid; idx < 40 * 60;  idx += 256) s_w2[idx] = fw2[idx];
    for (int idx = tid; idx < 5 * 40;   idx += 256) s_w3[idx] = fw3[idx];
    __syncthreads();

    const int b  = tid & 127;
    const int hb = tid >> 7;
    // stage 1: 120 -> 60, tanh  (hb=0: jb 0..4, hb=1: jb 5..9)
    for (int jb = hb * 5; jb < hb * 5 + 5; ++jb) {
        float acc[6];
#pragma unroll
        for (int j = 0; j < 6; j++) acc[j] = __ldg(fb1 + jb * 6 + j);
#pragma unroll 5
        for (int kt = 0; kt < 30; ++kt) {
            float x0 = s_x[b * 121 + 4 * kt + 0];
            float x1 = s_x[b * 121 + 4 * kt + 1];
            float x2 = s_x[b * 121 + 4 * kt + 2];
            float x3 = s_x[b * 121 + 4 * kt + 3];
#pragma unroll
            for (int j = 0; j < 6; j++) {
                float4 wv = *(const float4*)&s_w1[(jb * 6 + j) * 120 + 4 * kt];
                acc[j] = fmaf(x0, wv.x, acc[j]);
                acc[j] = fmaf(x1, wv.y, acc[j]);
                acc[j] = fmaf(x2, wv.z, acc[j]);
                acc[j] = fmaf(x3, wv.w, acc[j]);
            }
        }
#pragma unroll
        for (int j = 0; j < 6; j++) s_h1[b * 61 + jb * 6 + j] = tanh_f(acc[j]);
    }
    __syncthreads();
    // stage 2: 60 -> 40, tanh  (hb=0: jb 0..3, hb=1: jb 4..7)
    for (int jb = hb * 4; jb < hb * 4 + 4; ++jb) {
        float acc[5];
#pragma unroll
        for (int j = 0; j < 5; j++) acc[j] = __ldg(fb2 + jb * 5 + j);
#pragma unroll 5
        for (int kt = 0; kt < 15; ++kt) {
            float x0 = s_h1[b * 61 + 4 * kt + 0];
            float x1 = s_h1[b * 61 + 4 * kt + 1];
            float x2 = s_h1[b * 61 + 4 * kt + 2];
            float x3 = s_h1[b * 61 + 4 * kt + 3];
#pragma unroll
            for (int j = 0; j < 5; j++) {
                float4 wv = *(const float4*)&s_w2[(jb * 5 + j) * 60 + 4 * kt];
                acc[j] = fmaf(x0, wv.x, acc[j]);
                acc[j] = fmaf(x1, wv.y, acc[j]);
                acc[j] = fmaf(x2, wv.z, acc[j]);
                acc[j] = fmaf(x3, wv.w, acc[j]);
            }
        }
#pragma unroll
        for (int j = 0; j < 5; j++) s_h2[b * 41 + jb * 5 + j] = tanh_f(acc[j]);
    }
    __syncthreads();
    // stage 3: 40 -> 5 (no activation); hb=0: c 0..2, hb=1: c 3..4
#pragma unroll
    for (int cc = 0; cc < 3; cc++) {
        int c = hb * 3 + cc;
        if (c < 5) {
            float acc = __ldg(fb3 + c);
#pragma unroll
            for (int kt = 0; kt < 10; ++kt) {
                float4 wv = *(const float4*)&s_w3[c * 40 + 4 * kt];
                acc = fmaf(s_h2[b * 41 + 4 * kt + 0], wv.x, acc);
                acc = fmaf(s_h2[b * 41 + 4 * kt + 1], wv.y, acc);
                acc = fmaf(s_h2[b * 41 + 4 * kt + 2], wv.z, acc);
                acc = fmaf(s_h2[b * 41 + 4 * kt + 3], wv.w, acc);
            }
            g_logits[((size_t)(b * 5 + c)) * T_LEN + t] = acc;
        }
    }
}

// ---------------- softmax over t per (b,c) row; writes frame probs + row sums
__global__ __launch_bounds__(256)
void softmax_kernel(float* __restrict__ frame)
{
    const int row = blockIdx.x;      // b*5+c
    const int tid = threadIdx.x;
    const float* lp = g_logits + (size_t)row * T_LEN;

    float v[16];
    float mx = -1e30f;
#pragma unroll
    for (int i = 0; i < 16; i++) { v[i] = lp[tid + i * 256]; mx = fmaxf(mx, v[i]); }

    __shared__ float red[256];
    red[tid] = mx; __syncthreads();
    for (int o = 128; o > 0; o >>= 1) { if (tid < o) red[tid] = fmaxf(red[tid], red[tid + o]); __syncthreads(); }
    mx = red[0]; __syncthreads();

    float sum = 0.f;
#pragma unroll
    for (int i = 0; i < 16; i++) { v[i] = __expf(v[i] - mx); sum += v[i]; }
    red[tid] = sum; __syncthreads();
    for (int o = 128; o > 0; o >>= 1) { if (tid < o) red[tid] += red[tid + o]; __syncthreads(); }
    float inv = __fdividef(1.f, red[0]); __syncthreads();

    float ps = 0.f;
    float* fp = frame + (size_t)row * T_LEN;
#pragma unroll
    for (int i = 0; i < 16; i++) { float p = v[i] * inv; fp[tid + i * 256] = p; ps += p; }
    red[tid] = ps; __syncthreads();
    for (int o = 128; o > 0; o >>= 1) { if (tid < o) red[tid] += red[tid + o]; __syncthreads(); }
    if (tid == 0) g_msum[row] = red[0];
}

// ---------------- m head: softmax(5) -> relu(mw1) -> mw2 -> softmax(2)
__global__ void m_kernel(const float* __restrict__ mw1, const float* __restrict__ mb1,
                         const float* __restrict__ mw2, const float* __restrict__ mb2,
                         float* __restrict__ out_m)
{
    const int b = threadIdx.x;
    if (b >= NB) return;
    float s[5], mx = -1e30f;
#pragma unroll
    for (int c = 0; c < 5; c++) { s[c] = g_msum[b * 5 + c]; mx = fmaxf(mx, s[c]); }
    float sum = 0.f;
#pragma unroll
    for (int c = 0; c < 5; c++) { s[c] = __expf(s[c] - mx); sum += s[c]; }
    float inv = __fdividef(1.f, sum);
#pragma unroll
    for (int c = 0; c < 5; c++) s[c] *= inv;
    float a[5];
#pragma unroll
    for (int i = 0; i < 5; i++) {
        float t = mb1[i];
#pragma unroll
        for (int c = 0; c < 5; c++) t = fmaf(s[c], mw1[i * 5 + c], t);
        a[i] = fmaxf(t, 0.f);
    }
    float o0 = mb2[0], o1 = mb2[1];
#pragma unroll
    for (int i = 0; i < 5; i++) { o0 = fmaf(a[i], mw2[i], o0); o1 = fmaf(a[i], mw2[5 + i], o1); }
    float m2 = fmaxf(o0, o1);
    float e0 = __expf(o0 - m2), e1 = __expf(o1 - m2);
    float is = __fdividef(1.f, e0 + e1);
    out_m[b * 2 + 0] = e0 * is;
    out_m[b * 2 + 1] = e1 * is;
}

// ---------------- host ----------------
extern "C" void kernel_launch(void* const* d_in, const int* in_sizes, int n_in,
                              void* d_out, int out_size)
{
    const float* x     = (const float*)d_in[0];
    const float* w_ih0 = (const float*)d_in[1];
    const float* w_hh0 = (const float*)d_in[2];
    const float* b_ih0 = (const float*)d_in[3];
    const float* b_hh0 = (const float*)d_in[4];
    const float* w_ih1 = (const float*)d_in[5];
    const float* w_hh1 = (const float*)d_in[6];
    const float* b_ih1 = (const float*)d_in[7];
    const float* b_hh1 = (const float*)d_in[8];
    const float* w_ih2 = (const float*)d_in[9];
    const float* w_hh2 = (const float*)d_in[10];
    const float* b_ih2 = (const float*)d_in[11];
    const float* b_hh2 = (const float*)d_in[12];
    const float* fw1   = (const float*)d_in[13];
    const float* fb1   = (const float*)d_in[14];
    const float* fw2   = (const float*)d_in[15];
    const float* fb2   = (const float*)d_in[16];
    const float* fw3   = (const float*)d_in[17];
    const float* fb3   = (const float*)d_in[18];
    const float* mw1   = (const float*)d_in[19];
    const float* mb1   = (const float*)d_in[20];
    const float* mw2   = (const float*)d_in[21];
    const float* mb2   = (const float*)d_in[22];
    float* out = (float*)d_out;

    const int SM0 = 64  * (132 + 194) * 4;   // 83456 B
    const int SM1 = 120 * (132 + 194) * 4;   // 156480 B
    const int SMH = (128*121 + 60*120 + 128*61 + 40*60 + 128*41 + 5*40) * 4; // 153376 B

    cudaFuncSetAttribute(proj_kernel<64, true>,   cudaFuncAttributeMaxDynamicSharedMemorySize, SM0);
    cudaFuncSetAttribute(proj_kernel<120, false>, cudaFuncAttributeMaxDynamicSharedMemorySize, SM1);
    cudaFuncSetAttribute(head_kernel,             cudaFuncAttributeMaxDynamicSharedMemorySize, SMH);

    dim3 pg(T_LEN / 128, NB, 2);

    proj_kernel<64, true><<<pg, 512, SM0>>>(x, w_ih0, b_ih0);
    scan_kernel<<<NB, 256>>>(w_hh0, b_hh0);

    proj_kernel<120, false><<<pg, 512, SM1>>>(nullptr, w_ih1, b_ih1);
    scan_kernel<<<NB, 256>>>(w_hh1, b_hh1);

    proj_kernel<120, false><<<pg, 512, SM1>>>(nullptr, w_ih2, b_ih2);
    scan_kernel<<<NB, 256>>>(w_hh2, b_hh2);

    head_kernel<<<T_LEN, 256, SMH>>>(fw1, fb1, fw2, fb2, fw3, fb3);
    softmax_kernel<<<NB * 5, 256>>>(out);
    m_kernel<<<1, 128>>>(mw1, mb1, mw2, mb2, out + (size_t)NB * 5 * T_LEN);
}

// round 14
// speedup vs baseline: 1.0744x; 1.0744x over previous
#include <cuda_runtime.h>
#include <cstdint>

#define T_LEN 4096
#define NB    128
#define G3    180   // 3*H
#define HS    60

typedef unsigned long long ull;

// packed f32x2 helpers (sm_100a)
#define FMA2(d, a, b, c) asm("fma.rn.f32x2 %0, %1, %2, %3;" : "=l"(d) : "l"(a), "l"(b), "l"(c))
#define ADD2(d, a, b)    asm("add.rn.f32x2 %0, %1, %2;"    : "=l"(d) : "l"(a), "l"(b))
__device__ __forceinline__ ull pack2(float x, float y) {
    ull r; asm("mov.b64 %0, {%1,%2};" : "=l"(r) : "f"(x), "f"(y)); return r;
}
__device__ __forceinline__ void unpack2(float& lo, float& hi, ull v) {
    asm("mov.b64 {%0,%1}, %2;" : "=f"(lo), "=f"(hi) : "l"(v));
}
__device__ __forceinline__ float hsum2(ull a, ull b) {
    ull s; ADD2(s, a, b);
    float lo, hi; unpack2(lo, hi, s);
    return lo + hi;
}

// ---------------- scratch (static device globals; no allocations) ----------------
// gi layout: [d][b][t][g], padded both ends so deep prefetch over/underruns stay in-bounds.
__device__ __align__(16) float g_gi_raw[(size_t)2 * NB * T_LEN * G3 + 4096];
#define GI_BASE (g_gi_raw + 2048)
__device__ float g_y [(size_t)T_LEN * NB * 120];      // [t][b][2H]
__device__ float g_logits[(size_t)NB * 5 * T_LEN];    // [b][c][t]
__device__ float g_msum[NB * 5];

// HW tanh (MUFU.TANH, sm_75+): ~2e-5 abs err, single-op
__device__ __forceinline__ float tanh_f(float x) {
    float y; asm("tanh.approx.f32 %0, %1;" : "=f"(y) : "f"(x)); return y;
}
__device__ __forceinline__ float sigmoid_f(float x) {
    return fmaf(0.5f, tanh_f(0.5f * x), 0.5f);
}

// ---------------- input projection: 512 threads (R12 version, coalesced pair stores) ----
// gi[d][b][t][g] = b_ih[d][g] + sum_i in[t][b][i]*W[d][g][i]
template <int K, bool L0>
__global__ __launch_bounds__(512, 1)
void proj_kernel(const float* __restrict__ in,
                 const float* __restrict__ w_ih,
                 const float* __restrict__ b_ih)
{
    constexpr int TT  = 128;       // t-tile
    constexpr int TTP = 132;       // padded t stride (16B-aligned rows)
    constexpr int GP  = 194;       // padded g stride (even -> 8B pair loads)

    extern __shared__ float sm[];
    float* s_in = sm;              // [K][TTP]
    float* s_w  = sm + K * TTP;    // [K][GP]

    const int tb0 = blockIdx.x * TT;
    const int b   = blockIdx.y;
    const int d   = blockIdx.z;
    const int tid = threadIdx.x;

    if (L0) {
        // x: (B, K, T) -> s_in[i][t]   (coalesced over t)
        for (int idx = tid; idx < K * TT; idx += 512) {
            int i = idx / TT, t = idx % TT;
            s_in[i * TTP + t] = in[((size_t)b * K + i) * T_LEN + tb0 + t];
        }
    } else {
        // y: (T, B, 120) -> s_in[i][t] (coalesced over i)
        for (int idx = tid; idx < K * TT; idx += 512) {
            int t = idx / K, i = idx % K;
            s_in[i * TTP + t] = g_y[((size_t)(tb0 + t) * NB + b) * K + i];
        }
    }
    // weights: w_ih[d][g][k] -> s_w[k][g]
    const float* wd = w_ih + (size_t)d * G3 * K;
    for (int idx = tid; idx < G3 * K; idx += 512) {
        int g = idx / K, k = idx % K;
        s_w[k * GP + g] = wd[idx];
    }
    __syncthreads();

    const int ty = tid >> 5;   // 0..15 (8 t's each)
    const int tx = tid & 31;   // 0..31 (pair p = j*32+tx, g = 2p)

    ull acc[8][3];
#pragma unroll
    for (int i = 0; i < 8; i++)
#pragma unroll
        for (int j = 0; j < 3; j++) acc[i][j] = 0ull;

#pragma unroll 2
    for (int k = 0; k < K; k++) {
        const float* arow = s_in + k * TTP + ty * 8;
        float4 a0 = *(const float4*)(arow);
        float4 a1 = *(const float4*)(arow + 4);
        ull ap[8];
        ap[0] = pack2(a0.x, a0.x); ap[1] = pack2(a0.y, a0.y);
        ap[2] = pack2(a0.z, a0.z); ap[3] = pack2(a0.w, a0.w);
        ap[4] = pack2(a1.x, a1.x); ap[5] = pack2(a1.y, a1.y);
        ap[6] = pack2(a1.z, a1.z); ap[7] = pack2(a1.w, a1.w);
        const ull* wrow = (const ull*)(s_w + k * GP);
#pragma unroll
        for (int j = 0; j < 3; j++) {
            ull w2 = wrow[j * 32 + tx];   // pairs 0..95; rows have 97 pairs (GP=194)
#pragma unroll
            for (int i = 0; i < 8; i++) FMA2(acc[i][j], ap[i], w2, acc[i][j]);
        }
    }

    const float2* bp2 = (const float2*)(b_ih + d * G3);   // 8B aligned (d*180 even)
    float* gout = GI_BASE + (((size_t)d * NB + b) * T_LEN) * G3;
#pragma unroll
    for (int j = 0; j < 3; j++) {
        int p = j * 32 + tx;
        if (p < G3 / 2) {
            float2 bb = bp2[p];
            ull bbp = pack2(bb.x, bb.y);
#pragma unroll
            for (int i = 0; i < 8; i++) {
                int t = tb0 + ty * 8 + i;
                ull v; ADD2(v, acc[i][j], bbp);
                *(ull*)&gout[(size_t)t * G3 + 2 * p] = v;
            }
        }
    }
}

// ---------------- GRU scan: one CTA per batch, BOTH directions (256 threads).
// warps 0-3 = fwd (d=0), warps 4-7 = bwd (d=1); per-direction named barriers.
// Statically-indexed depth-8 prefetch ring: slot u consumed at step s, reloaded for s+8.
__global__ __launch_bounds__(256)
void scan_kernel(const float* __restrict__ w_hh,
                 const float* __restrict__ b_hh)
{
    const int b    = blockIdx.x;
    const int tid  = threadIdx.x;
    const int d    = tid >> 7;          // 0 or 1 (warp-aligned groups)
    const int lt   = tid & 127;         // lane-in-direction
    const int j    = lt >> 1;
    const int half = lt & 1;
    const int jeff = (j < HS) ? j : (HS - 1);   // keep lanes converged

    __shared__ __align__(16) float s_h[2][2][64];   // [dir][buf][h]

    // half of each gate-row of W_hh -> registers (packed pairs)
    ull wr[15], wz[15], wn[15];
    {
        const ull* pr = (const ull*)(w_hh + ((size_t)d * G3 + jeff) * HS + half * 30);
        const ull* pz = (const ull*)(w_hh + ((size_t)d * G3 + jeff + HS) * HS + half * 30);
        const ull* pn = (const ull*)(w_hh + ((size_t)d * G3 + jeff + 2 * HS) * HS + half * 30);
#pragma unroll
        for (int k = 0; k < 15; k++) { wr[k] = pr[k]; wz[k] = pz[k]; wn[k] = pn[k]; }
    }
    float br = 0.f, bz = 0.f, bn = 0.f;
    if (half == 0) {
        br = b_hh[d * G3 + jeff];
        bz = b_hh[d * G3 + jeff + HS];
        bn = b_hh[d * G3 + jeff + 2 * HS];
    }
    if (lt < 64) { s_h[d][0][lt] = 0.f; s_h[d][1][lt] = 0.f; }
    __syncthreads();

    const long long dstep = (d ? -(long long)G3 : (long long)G3);
    const long long ystep = (d ? -(long long)(NB * 120) : (long long)(NB * 120));
    const size_t tstart = d ? (size_t)(T_LEN - 1) : 0;

    const float* q = GI_BASE + (((size_t)d * NB + b) * T_LEN + tstart) * G3 + jeff;
    float* yp = g_y + tstart * (NB * 120) + (size_t)b * 120 + d * HS + jeff;

    // depth-8 prefetch ring, statically indexed (no shifts; LDG consumed 8 steps later).
    // Over/underruns land in adjacent gi regions or the array pad -> always in-bounds.
    float fr[8], fz[8], fn[8];
#pragma unroll
    for (int i = 0; i < 8; i++) {
        fr[i] = fz[i] = fn[i] = 0.f;
        if (half == 0) { fr[i] = __ldg(q); fz[i] = __ldg(q + HS); fn[i] = __ldg(q + 2 * HS); }
        q += dstep;
    }

    const int bar_id = 1 + d;   // named barrier per direction (warps aligned)

    int cb = 0;
    for (int s0 = 0; s0 < T_LEN; s0 += 8) {
#pragma unroll
        for (int u = 0; u < 8; u++) {
            float gir = fr[u], giz = fz[u], gin = fn[u];
            if (half == 0) {   // reload slot u for step s0+u+8 (unconditional; pad covers edges)
                fr[u] = __ldg(q); fz[u] = __ldg(q + HS); fn[u] = __ldg(q + 2 * HS);
            }
            q += dstep;

            // partial dots over this half's 30 h-elements
            ull a_r0 = 0, a_r1 = 0, a_z0 = 0, a_z1 = 0, a_n0 = 0, a_n1 = 0;
            const ull* hv = (const ull*)&s_h[d][cb][half * 30];
#pragma unroll
            for (int k = 0; k < 15; k++) {
                ull hk = hv[k];
                if (k & 1) {
                    FMA2(a_r1, wr[k], hk, a_r1);
                    FMA2(a_z1, wz[k], hk, a_z1);
                    FMA2(a_n1, wn[k], hk, a_n1);
                } else {
                    FMA2(a_r0, wr[k], hk, a_r0);
                    FMA2(a_z0, wz[k], hk, a_z0);
                    FMA2(a_n0, wn[k], hk, a_n0);
                }
            }
            float ghr = hsum2(a_r0, a_r1);
            float ghz = hsum2(a_z0, a_z1);
            float ghn = hsum2(a_n0, a_n1);
            ghr += __shfl_xor_sync(0xffffffffu, ghr, 1);
            ghz += __shfl_xor_sync(0xffffffffu, ghz, 1);
            ghn += __shfl_xor_sync(0xffffffffu, ghn, 1);

            if (half == 0 && j < HS) {
                float r = sigmoid_f(gir + (br + ghr));
                float z = sigmoid_f(giz + (bz + ghz));
                float n = tanh_f(fmaf(r, bn + ghn, gin));
                float h_old = s_h[d][cb][j];
                float hnew = fmaf(z, h_old - n, n);     // (1-z)*n + z*h
                s_h[d][cb ^ 1][j] = hnew;
                *yp = hnew;
            }
            yp += ystep;
            asm volatile("bar.sync %0, 128;" :: "r"(bar_id) : "memory");
            cb ^= 1;
        }
    }
}

// ---------------- frame head: (T,B,120) -> logits (b,c,t). One CTA per t.
// 256 threads: b = tid&127, hb = tid>>7; each half computes half the outputs per stage.
__global__ __launch_bounds__(256)
void head_kernel(const float* __restrict__ fw1, const float* __restrict__ fb1,
                 const float* __restrict__ fw2, const float* __restrict__ fb2,
                 const float* __restrict__ fw3, const float* __restrict__ fb3)
{
    extern __shared__ float sm[];
    float* s_x  = sm;                    // [128][121]
    float* s_w1 = s_x  + 128 * 121;      // [60][120]
    float* s_h1 = s_w1 + 60 * 120;       // [128][61]
    float* s_w2 = s_h1 + 128 * 61;       // [40][60]
    float* s_h2 = s_w2 + 40 * 60;        // [128][41]
    float* s_w3 = s_h2 + 128 * 41;       // [5][40]

    const int t   = blockIdx.x;
    const int tid = threadIdx.x;

    for (int idx = tid; idx < 128 * 120; idx += 256) {
        int r = idx / 120, i = idx % 120;
        s_x[r * 121 + i] = g_y[((size_t)t * NB + r) * 120 + i];
    }
    for (int idx = tid; idx < 60 * 120; idx += 256) s_w1[idx] = fw1[idx];
    for (int idx = tid; idx < 40 * 60;  idx += 256) s_w2[idx] = fw2[idx];
    for (int idx = tid; idx < 5 * 40;   idx += 256) s_w3[idx] = fw3[idx];
    __syncthreads();

    const int b  = tid & 127;
    const int hb = tid >> 7;
    // stage 1: 120 -> 60, tanh  (hb=0: jb 0..4, hb=1: jb 5..9)
    for (int jb = hb * 5; jb < hb * 5 + 5; ++jb) {
        float acc[6];
#pragma unroll
        for (int j = 0; j < 6; j++) acc[j] = __ldg(fb1 + jb * 6 + j);
#pragma unroll 5
        for (int kt = 0; kt < 30; ++kt) {
            float x0 = s_x[b * 121 + 4 * kt + 0];
            float x1 = s_x[b * 121 + 4 * kt + 1];
            float x2 = s_x[b * 121 + 4 * kt + 2];
            float x3 = s_x[b * 121 + 4 * kt + 3];
#pragma unroll
            for (int j = 0; j < 6; j++) {
                float4 wv = *(const float4*)&s_w1[(jb * 6 + j) * 120 + 4 * kt];
                acc[j] = fmaf(x0, wv.x, acc[j]);
                acc[j] = fmaf(x1, wv.y, acc[j]);
                acc[j] = fmaf(x2, wv.z, acc[j]);
                acc[j] = fmaf(x3, wv.w, acc[j]);
            }
        }
#pragma unroll
        for (int j = 0; j < 6; j++) s_h1[b * 61 + jb * 6 + j] = tanh_f(acc[j]);
    }
    __syncthreads();
    // stage 2: 60 -> 40, tanh  (hb=0: jb 0..3, hb=1: jb 4..7)
    for (int jb = hb * 4; jb < hb * 4 + 4; ++jb) {
        float acc[5];
#pragma unroll
        for (int j = 0; j < 5; j++) acc[j] = __ldg(fb2 + jb * 5 + j);
#pragma unroll 5
        for (int kt = 0; kt < 15; ++kt) {
            float x0 = s_h1[b * 61 + 4 * kt + 0];
            float x1 = s_h1[b * 61 + 4 * kt + 1];
            float x2 = s_h1[b * 61 + 4 * kt + 2];
            float x3 = s_h1[b * 61 + 4 * kt + 3];
#pragma unroll
            for (int j = 0; j < 5; j++) {
                float4 wv = *(const float4*)&s_w2[(jb * 5 + j) * 60 + 4 * kt];
                acc[j] = fmaf(x0, wv.x, acc[j]);
                acc[j] = fmaf(x1, wv.y, acc[j]);
                acc[j] = fmaf(x2, wv.z, acc[j]);
                acc[j] = fmaf(x3, wv.w, acc[j]);
            }
        }
#pragma unroll
        for (int j = 0; j < 5; j++) s_h2[b * 41 + jb * 5 + j] = tanh_f(acc[j]);
    }
    __syncthreads();
    // stage 3: 40 -> 5 (no activation); hb=0: c 0..2, hb=1: c 3..4
#pragma unroll
    for (int cc = 0; cc < 3; cc++) {
        int c = hb * 3 + cc;
        if (c < 5) {
            float acc = __ldg(fb3 + c);
#pragma unroll
            for (int kt = 0; kt < 10; ++kt) {
                float4 wv = *(const float4*)&s_w3[c * 40 + 4 * kt];
                acc = fmaf(s_h2[b * 41 + 4 * kt + 0], wv.x, acc);
                acc = fmaf(s_h2[b * 41 + 4 * kt + 1], wv.y, acc);
                acc = fmaf(s_h2[b * 41 + 4 * kt + 2], wv.z, acc);
                acc = fmaf(s_h2[b * 41 + 4 * kt + 3], wv.w, acc);
            }
            g_logits[((size_t)(b * 5 + c)) * T_LEN + t] = acc;
        }
    }
}

// ---------------- softmax over t per (b,c) row; writes frame probs + row sums
__global__ __launch_bounds__(256)
void softmax_kernel(float* __restrict__ frame)
{
    const int row = blockIdx.x;      // b*5+c
    const int tid = threadIdx.x;
    const float* lp = g_logits + (size_t)row * T_LEN;

    float v[16];
    float mx = -1e30f;
#pragma unroll
    for (int i = 0; i < 16; i++) { v[i] = lp[tid + i * 256]; mx = fmaxf(mx, v[i]); }

    __shared__ float red[256];
    red[tid] = mx; __syncthreads();
    for (int o = 128; o > 0; o >>= 1) { if (tid < o) red[tid] = fmaxf(red[tid], red[tid + o]); __syncthreads(); }
    mx = red[0]; __syncthreads();

    float sum = 0.f;
#pragma unroll
    for (int i = 0; i < 16; i++) { v[i] = __expf(v[i] - mx); sum += v[i]; }
    red[tid] = sum; __syncthreads();
    for (int o = 128; o > 0; o >>= 1) { if (tid < o) red[tid] += red[tid + o]; __syncthreads(); }
    float inv = __fdividef(1.f, red[0]); __syncthreads();

    float ps = 0.f;
    float* fp = frame + (size_t)row * T_LEN;
#pragma unroll
    for (int i = 0; i < 16; i++) { float p = v[i] * inv; fp[tid + i * 256] = p; ps += p; }
    red[tid] = ps; __syncthreads();
    for (int o = 128; o > 0; o >>= 1) { if (tid < o) red[tid] += red[tid + o]; __syncthreads(); }
    if (tid == 0) g_msum[row] = red[0];
}

// ---------------- m head: softmax(5) -> relu(mw1) -> mw2 -> softmax(2)
__global__ void m_kernel(const float* __restrict__ mw1, const float* __restrict__ mb1,
                         const float* __restrict__ mw2, const float* __restrict__ mb2,
                         float* __restrict__ out_m)
{
    const int b = threadIdx.x;
    if (b >= NB) return;
    float s[5], mx = -1e30f;
#pragma unroll
    for (int c = 0; c < 5; c++) { s[c] = g_msum[b * 5 + c]; mx = fmaxf(mx, s[c]); }
    float sum = 0.f;
#pragma unroll
    for (int c = 0; c < 5; c++) { s[c] = __expf(s[c] - mx); sum += s[c]; }
    float inv = __fdividef(1.f, sum);
#pragma unroll
    for (int c = 0; c < 5; c++) s[c] *= inv;
    float a[5];
#pragma unroll
    for (int i = 0; i < 5; i++) {
        float t = mb1[i];
#pragma unroll
        for (int c = 0; c < 5; c++) t = fmaf(s[c], mw1[i * 5 + c], t);
        a[i] = fmaxf(t, 0.f);
    }
    float o0 = mb2[0], o1 = mb2[1];
#pragma unroll
    for (int i = 0; i < 5; i++) { o0 = fmaf(a[i], mw2[i], o0); o1 = fmaf(a[i], mw2[5 + i], o1); }
    float m2 = fmaxf(o0, o1);
    float e0 = __expf(o0 - m2), e1 = __expf(o1 - m2);
    float is = __fdividef(1.f, e0 + e1);
    out_m[b * 2 + 0] = e0 * is;
    out_m[b * 2 + 1] = e1 * is;
}

// ---------------- host ----------------
extern "C" void kernel_launch(void* const* d_in, const int* in_sizes, int n_in,
                              void* d_out, int out_size)
{
    const float* x     = (const float*)d_in[0];
    const float* w_ih0 = (const float*)d_in[1];
    const float* w_hh0 = (const float*)d_in[2];
    const float* b_ih0 = (const float*)d_in[3];
    const float* b_hh0 = (const float*)d_in[4];
    const float* w_ih1 = (const float*)d_in[5];
    const float* w_hh1 = (const float*)d_in[6];
    const float* b_ih1 = (const float*)d_in[7];
    const float* b_hh1 = (const float*)d_in[8];
    const float* w_ih2 = (const float*)d_in[9];
    const float* w_hh2 = (const float*)d_in[10];
    const float* b_ih2 = (const float*)d_in[11];
    const float* b_hh2 = (const float*)d_in[12];
    const float* fw1   = (const float*)d_in[13];
    const float* fb1   = (const float*)d_in[14];
    const float* fw2   = (const float*)d_in[15];
    const float* fb2   = (const float*)d_in[16];
    const float* fw3   = (const float*)d_in[17];
    const float* fb3   = (const float*)d_in[18];
    const float* mw1   = (const float*)d_in[19];
    const float* mb1   = (const float*)d_in[20];
    const float* mw2   = (const float*)d_in[21];
    const float* mb2   = (const float*)d_in[22];
    float* out = (float*)d_out;

    const int SM0 = 64  * (132 + 194) * 4;   // 83456 B
    const int SM1 = 120 * (132 + 194) * 4;   // 156480 B
    const int SMH = (128*121 + 60*120 + 128*61 + 40*60 + 128*41 + 5*40) * 4; // 153376 B

    cudaFuncSetAttribute(proj_kernel<64, true>,   cudaFuncAttributeMaxDynamicSharedMemorySize, SM0);
    cudaFuncSetAttribute(proj_kernel<120, false>, cudaFuncAttributeMaxDynamicSharedMemorySize, SM1);
    cudaFuncSetAttribute(head_kernel,             cudaFuncAttributeMaxDynamicSharedMemorySize, SMH);

    dim3 pg(T_LEN / 128, NB, 2);

    proj_kernel<64, true><<<pg, 512, SM0>>>(x, w_ih0, b_ih0);
    scan_kernel<<<NB, 256>>>(w_hh0, b_hh0);

    proj_kernel<120, false><<<pg, 512, SM1>>>(nullptr, w_ih1, b_ih1);
    scan_kernel<<<NB, 256>>>(w_hh1, b_hh1);

    proj_kernel<120, false><<<pg, 512, SM1>>>(nullptr, w_ih2, b_ih2);
    scan_kernel<<<NB, 256>>>(w_hh2, b_hh2);

    head_kernel<<<T_LEN, 256, SMH>>>(fw1, fb1, fw2, fb2, fw3, fb3);
    softmax_kernel<<<NB * 5, 256>>>(out);
    m_kernel<<<1, 128>>>(mw1, mb1, mw2, mb2, out + (size_t)NB * 5 * T_LEN);
}

// round 15
// speedup vs baseline: 1.0855x; 1.0104x over previous
#include <cuda_runtime.h>
#include <cstdint>

#define T_LEN 4096
#define NB    128
#define G3    180   // 3*H
#define HS    60

typedef unsigned long long ull;

// packed f32x2 helpers (sm_100a)
#define FMA2(d, a, b, c) asm("fma.rn.f32x2 %0, %1, %2, %3;" : "=l"(d) : "l"(a), "l"(b), "l"(c))
#define ADD2(d, a, b)    asm("add.rn.f32x2 %0, %1, %2;"    : "=l"(d) : "l"(a), "l"(b))
__device__ __forceinline__ ull pack2(float x, float y) {
    ull r; asm("mov.b64 %0, {%1,%2};" : "=l"(r) : "f"(x), "f"(y)); return r;
}
__device__ __forceinline__ void unpack2(float& lo, float& hi, ull v) {
    asm("mov.b64 {%0,%1}, %2;" : "=f"(lo), "=f"(hi) : "l"(v));
}
__device__ __forceinline__ float hsum2(ull a, ull b) {
    ull s; ADD2(s, a, b);
    float lo, hi; unpack2(lo, hi, s);
    return lo + hi;
}

// ---------------- scratch (static device globals; no allocations) ----------------
// gi layout: [d][b][t][g], padded both ends so deep prefetch over/underruns stay in-bounds.
__device__ __align__(16) float g_gi_raw[(size_t)2 * NB * T_LEN * G3 + 4096];
#define GI_BASE (g_gi_raw + 2048)
__device__ float g_y [(size_t)T_LEN * NB * 120];      // [t][b][2H]
__device__ float g_logits[(size_t)NB * 5 * T_LEN];    // [b][c][t]
__device__ float g_msum[NB * 5];

// HW tanh (MUFU.TANH, sm_75+): ~2e-5 abs err, single-op
__device__ __forceinline__ float tanh_f(float x) {
    float y; asm("tanh.approx.f32 %0, %1;" : "=f"(y) : "f"(x)); return y;
}
__device__ __forceinline__ float sigmoid_f(float x) {
    return fmaf(0.5f, tanh_f(0.5f * x), 0.5f);
}

// ---------------- input projection: 512 threads (frozen R12 version) ----------------
// gi[d][b][t][g] = b_ih[d][g] + sum_i in[t][b][i]*W[d][g][i]
template <int K, bool L0>
__global__ __launch_bounds__(512, 1)
void proj_kernel(const float* __restrict__ in,
                 const float* __restrict__ w_ih,
                 const float* __restrict__ b_ih)
{
    constexpr int TT  = 128;       // t-tile
    constexpr int TTP = 132;       // padded t stride (16B-aligned rows)
    constexpr int GP  = 194;       // padded g stride (even -> 8B pair loads)

    extern __shared__ float sm[];
    float* s_in = sm;              // [K][TTP]
    float* s_w  = sm + K * TTP;    // [K][GP]

    const int tb0 = blockIdx.x * TT;
    const int b   = blockIdx.y;
    const int d   = blockIdx.z;
    const int tid = threadIdx.x;

    if (L0) {
        // x: (B, K, T) -> s_in[i][t]   (coalesced over t)
        for (int idx = tid; idx < K * TT; idx += 512) {
            int i = idx / TT, t = idx % TT;
            s_in[i * TTP + t] = in[((size_t)b * K + i) * T_LEN + tb0 + t];
        }
    } else {
        // y: (T, B, 120) -> s_in[i][t] (coalesced over i)
        for (int idx = tid; idx < K * TT; idx += 512) {
            int t = idx / K, i = idx % K;
            s_in[i * TTP + t] = g_y[((size_t)(tb0 + t) * NB + b) * K + i];
        }
    }
    // weights: w_ih[d][g][k] -> s_w[k][g]
    const float* wd = w_ih + (size_t)d * G3 * K;
    for (int idx = tid; idx < G3 * K; idx += 512) {
        int g = idx / K, k = idx % K;
        s_w[k * GP + g] = wd[idx];
    }
    __syncthreads();

    const int ty = tid >> 5;   // 0..15 (8 t's each)
    const int tx = tid & 31;   // 0..31 (pair p = j*32+tx, g = 2p)

    ull acc[8][3];
#pragma unroll
    for (int i = 0; i < 8; i++)
#pragma unroll
        for (int j = 0; j < 3; j++) acc[i][j] = 0ull;

#pragma unroll 2
    for (int k = 0; k < K; k++) {
        const float* arow = s_in + k * TTP + ty * 8;
        float4 a0 = *(const float4*)(arow);
        float4 a1 = *(const float4*)(arow + 4);
        ull ap[8];
        ap[0] = pack2(a0.x, a0.x); ap[1] = pack2(a0.y, a0.y);
        ap[2] = pack2(a0.z, a0.z); ap[3] = pack2(a0.w, a0.w);
        ap[4] = pack2(a1.x, a1.x); ap[5] = pack2(a1.y, a1.y);
        ap[6] = pack2(a1.z, a1.z); ap[7] = pack2(a1.w, a1.w);
        const ull* wrow = (const ull*)(s_w + k * GP);
#pragma unroll
        for (int j = 0; j < 3; j++) {
            ull w2 = wrow[j * 32 + tx];   // pairs 0..95; rows have 97 pairs (GP=194)
#pragma unroll
            for (int i = 0; i < 8; i++) FMA2(acc[i][j], ap[i], w2, acc[i][j]);
        }
    }

    const float2* bp2 = (const float2*)(b_ih + d * G3);   // 8B aligned (d*180 even)
    float* gout = GI_BASE + (((size_t)d * NB + b) * T_LEN) * G3;
#pragma unroll
    for (int j = 0; j < 3; j++) {
        int p = j * 32 + tx;
        if (p < G3 / 2) {
            float2 bb = bp2[p];
            ull bbp = pack2(bb.x, bb.y);
#pragma unroll
            for (int i = 0; i < 8; i++) {
                int t = tb0 + ty * 8 + i;
                ull v; ADD2(v, acc[i][j], bbp);
                *(ull*)&gout[(size_t)t * G3 + 2 * p] = v;
            }
        }
    }
}

// ---------------- GRU scan (FROZEN): one CTA per batch, both directions (256 threads).
// warps 0-3 = fwd (d=0), warps 4-7 = bwd (d=1); per-direction named barriers.
// Statically-indexed depth-8 prefetch ring: slot u consumed at step s, reloaded for s+8.
__global__ __launch_bounds__(256)
void scan_kernel(const float* __restrict__ w_hh,
                 const float* __restrict__ b_hh)
{
    const int b    = blockIdx.x;
    const int tid  = threadIdx.x;
    const int d    = tid >> 7;          // 0 or 1 (warp-aligned groups)
    const int lt   = tid & 127;         // lane-in-direction
    const int j    = lt >> 1;
    const int half = lt & 1;
    const int jeff = (j < HS) ? j : (HS - 1);   // keep lanes converged

    __shared__ __align__(16) float s_h[2][2][64];   // [dir][buf][h]

    // half of each gate-row of W_hh -> registers (packed pairs)
    ull wr[15], wz[15], wn[15];
    {
        const ull* pr = (const ull*)(w_hh + ((size_t)d * G3 + jeff) * HS + half * 30);
        const ull* pz = (const ull*)(w_hh + ((size_t)d * G3 + jeff + HS) * HS + half * 30);
        const ull* pn = (const ull*)(w_hh + ((size_t)d * G3 + jeff + 2 * HS) * HS + half * 30);
#pragma unroll
        for (int k = 0; k < 15; k++) { wr[k] = pr[k]; wz[k] = pz[k]; wn[k] = pn[k]; }
    }
    float br = 0.f, bz = 0.f, bn = 0.f;
    if (half == 0) {
        br = b_hh[d * G3 + jeff];
        bz = b_hh[d * G3 + jeff + HS];
        bn = b_hh[d * G3 + jeff + 2 * HS];
    }
    if (lt < 64) { s_h[d][0][lt] = 0.f; s_h[d][1][lt] = 0.f; }
    __syncthreads();

    const long long dstep = (d ? -(long long)G3 : (long long)G3);
    const long long ystep = (d ? -(long long)(NB * 120) : (long long)(NB * 120));
    const size_t tstart = d ? (size_t)(T_LEN - 1) : 0;

    const float* q = GI_BASE + (((size_t)d * NB + b) * T_LEN + tstart) * G3 + jeff;
    float* yp = g_y + tstart * (NB * 120) + (size_t)b * 120 + d * HS + jeff;

    // depth-8 prefetch ring, statically indexed (no shifts; LDG consumed 8 steps later).
    // Over/underruns land in adjacent gi regions or the array pad -> always in-bounds.
    float fr[8], fz[8], fn[8];
#pragma unroll
    for (int i = 0; i < 8; i++) {
        fr[i] = fz[i] = fn[i] = 0.f;
        if (half == 0) { fr[i] = __ldg(q); fz[i] = __ldg(q + HS); fn[i] = __ldg(q + 2 * HS); }
        q += dstep;
    }

    const int bar_id = 1 + d;   // named barrier per direction (warps aligned)

    int cb = 0;
    for (int s0 = 0; s0 < T_LEN; s0 += 8) {
#pragma unroll
        for (int u = 0; u < 8; u++) {
            float gir = fr[u], giz = fz[u], gin = fn[u];
            if (half == 0) {   // reload slot u for step s0+u+8 (unconditional; pad covers edges)
                fr[u] = __ldg(q); fz[u] = __ldg(q + HS); fn[u] = __ldg(q + 2 * HS);
            }
            q += dstep;

            // partial dots over this half's 30 h-elements
            ull a_r0 = 0, a_r1 = 0, a_z0 = 0, a_z1 = 0, a_n0 = 0, a_n1 = 0;
            const ull* hv = (const ull*)&s_h[d][cb][half * 30];
#pragma unroll
            for (int k = 0; k < 15; k++) {
                ull hk = hv[k];
                if (k & 1) {
                    FMA2(a_r1, wr[k], hk, a_r1);
                    FMA2(a_z1, wz[k], hk, a_z1);
                    FMA2(a_n1, wn[k], hk, a_n1);
                } else {
                    FMA2(a_r0, wr[k], hk, a_r0);
                    FMA2(a_z0, wz[k], hk, a_z0);
                    FMA2(a_n0, wn[k], hk, a_n0);
                }
            }
            float ghr = hsum2(a_r0, a_r1);
            float ghz = hsum2(a_z0, a_z1);
            float ghn = hsum2(a_n0, a_n1);
            ghr += __shfl_xor_sync(0xffffffffu, ghr, 1);
            ghz += __shfl_xor_sync(0xffffffffu, ghz, 1);
            ghn += __shfl_xor_sync(0xffffffffu, ghn, 1);

            if (half == 0 && j < HS) {
                float r = sigmoid_f(gir + (br + ghr));
                float z = sigmoid_f(giz + (bz + ghz));
                float n = tanh_f(fmaf(r, bn + ghn, gin));
                float h_old = s_h[d][cb][j];
                float hnew = fmaf(z, h_old - n, n);     // (1-z)*n + z*h
                s_h[d][cb ^ 1][j] = hnew;
                *yp = hnew;
            }
            yp += ystep;
            asm volatile("bar.sync %0, 128;" :: "r"(bar_id) : "memory");
            cb ^= 1;
        }
    }
}

// ---------------- frame head: (T,B,120) -> logits (b,c,t). One CTA per t, 512 threads.
// b = tid&127, hb = tid>>7 (0..3); stage loops split 4-way across hb.
// Padded strides 124/68/44: 16B-aligned LDS.128, conflict-free phases.
__global__ __launch_bounds__(512)
void head_kernel(const float* __restrict__ fw1, const float* __restrict__ fb1,
                 const float* __restrict__ fw2, const float* __restrict__ fb2,
                 const float* __restrict__ fw3, const float* __restrict__ fb3)
{
    constexpr int XP = 124, H1P = 68, H2P = 44;
    extern __shared__ float sm[];
    float* s_x  = sm;                    // [128][XP]
    float* s_w1 = s_x  + 128 * XP;       // [60][120]
    float* s_h1 = s_w1 + 60 * 120;       // [128][H1P]
    float* s_w2 = s_h1 + 128 * H1P;      // [40][60]
    float* s_h2 = s_w2 + 40 * 60;        // [128][H2P]
    float* s_w3 = s_h2 + 128 * H2P;      // [5][40]

    const int t   = blockIdx.x;
    const int tid = threadIdx.x;

    for (int idx = tid; idx < 128 * 120; idx += 512) {
        int r = idx / 120, i = idx % 120;
        s_x[r * XP + i] = g_y[((size_t)t * NB + r) * 120 + i];
    }
    for (int idx = tid; idx < 60 * 120; idx += 512) s_w1[idx] = fw1[idx];
    for (int idx = tid; idx < 40 * 60;  idx += 512) s_w2[idx] = fw2[idx];
    for (int idx = tid; idx < 5 * 40;   idx += 512) s_w3[idx] = fw3[idx];
    __syncthreads();

    const int b  = tid & 127;
    const int hb = tid >> 7;   // 0..3
    // stage 1: 120 -> 60, tanh  (jb = hb, hb+4, hb+8 -> 10 total)
    for (int jb = hb; jb < 10; jb += 4) {
        float acc[6];
#pragma unroll
        for (int j = 0; j < 6; j++) acc[j] = __ldg(fb1 + jb * 6 + j);
#pragma unroll 5
        for (int kt = 0; kt < 30; ++kt) {
            float4 xv = *(const float4*)&s_x[b * XP + 4 * kt];
#pragma unroll
            for (int j = 0; j < 6; j++) {
                float4 wv = *(const float4*)&s_w1[(jb * 6 + j) * 120 + 4 * kt];
                acc[j] = fmaf(xv.x, wv.x, acc[j]);
                acc[j] = fmaf(xv.y, wv.y, acc[j]);
                acc[j] = fmaf(xv.z, wv.z, acc[j]);
                acc[j] = fmaf(xv.w, wv.w, acc[j]);
            }
        }
#pragma unroll
        for (int j = 0; j < 6; j++) s_h1[b * H1P + jb * 6 + j] = tanh_f(acc[j]);
    }
    __syncthreads();
    // stage 2: 60 -> 40, tanh  (jb = hb*2, hb*2+1)
    for (int jb = hb * 2; jb < hb * 2 + 2; ++jb) {
        float acc[5];
#pragma unroll
        for (int j = 0; j < 5; j++) acc[j] = __ldg(fb2 + jb * 5 + j);
#pragma unroll 5
        for (int kt = 0; kt < 15; ++kt) {
            float4 xv = *(const float4*)&s_h1[b * H1P + 4 * kt];
#pragma unroll
            for (int j = 0; j < 5; j++) {
                float4 wv = *(const float4*)&s_w2[(jb * 5 + j) * 60 + 4 * kt];
                acc[j] = fmaf(xv.x, wv.x, acc[j]);
                acc[j] = fmaf(xv.y, wv.y, acc[j]);
                acc[j] = fmaf(xv.z, wv.z, acc[j]);
                acc[j] = fmaf(xv.w, wv.w, acc[j]);
            }
        }
#pragma unroll
        for (int j = 0; j < 5; j++) s_h2[b * H2P + jb * 5 + j] = tanh_f(acc[j]);
    }
    __syncthreads();
    // stage 3: 40 -> 5 (no activation); c = hb, hb+4
    for (int c = hb; c < 5; c += 4) {
        float acc = __ldg(fb3 + c);
#pragma unroll
        for (int kt = 0; kt < 10; ++kt) {
            float4 xv = *(const float4*)&s_h2[b * H2P + 4 * kt];
            float4 wv = *(const float4*)&s_w3[c * 40 + 4 * kt];
            acc = fmaf(xv.x, wv.x, acc);
            acc = fmaf(xv.y, wv.y, acc);
            acc = fmaf(xv.z, wv.z, acc);
            acc = fmaf(xv.w, wv.w, acc);
        }
        g_logits[((size_t)(b * 5 + c)) * T_LEN + t] = acc;
    }
}

// ---------------- softmax over t per (b,c) row; writes frame probs + row sums
__global__ __launch_bounds__(256)
void softmax_kernel(float* __restrict__ frame)
{
    const int row = blockIdx.x;      // b*5+c
    const int tid = threadIdx.x;
    const float* lp = g_logits + (size_t)row * T_LEN;

    float v[16];
    float mx = -1e30f;
#pragma unroll
    for (int i = 0; i < 16; i++) { v[i] = lp[tid + i * 256]; mx = fmaxf(mx, v[i]); }

    __shared__ float red[256];
    red[tid] = mx; __syncthreads();
    for (int o = 128; o > 0; o >>= 1) { if (tid < o) red[tid] = fmaxf(red[tid], red[tid + o]); __syncthreads(); }
    mx = red[0]; __syncthreads();

    float sum = 0.f;
#pragma unroll
    for (int i = 0; i < 16; i++) { v[i] = __expf(v[i] - mx); sum += v[i]; }
    red[tid] = sum; __syncthreads();
    for (int o = 128; o > 0; o >>= 1) { if (tid < o) red[tid] += red[tid + o]; __syncthreads(); }
    float inv = __fdividef(1.f, red[0]); __syncthreads();

    float ps = 0.f;
    float* fp = frame + (size_t)row * T_LEN;
#pragma unroll
    for (int i = 0; i < 16; i++) { float p = v[i] * inv; fp[tid + i * 256] = p; ps += p; }
    red[tid] = ps; __syncthreads();
    for (int o = 128; o > 0; o >>= 1) { if (tid < o) red[tid] += red[tid + o]; __syncthreads(); }
    if (tid == 0) g_msum[row] = red[0];
}

// ---------------- m head: softmax(5) -> relu(mw1) -> mw2 -> softmax(2)
__global__ void m_kernel(const float* __restrict__ mw1, const float* __restrict__ mb1,
                         const float* __restrict__ mw2, const float* __restrict__ mb2,
                         float* __restrict__ out_m)
{
    const int b = threadIdx.x;
    if (b >= NB) return;
    float s[5], mx = -1e30f;
#pragma unroll
    for (int c = 0; c < 5; c++) { s[c] = g_msum[b * 5 + c]; mx = fmaxf(mx, s[c]); }
    float sum = 0.f;
#pragma unroll
    for (int c = 0; c < 5; c++) { s[c] = __expf(s[c] - mx); sum += s[c]; }
    float inv = __fdividef(1.f, sum);
#pragma unroll
    for (int c = 0; c < 5; c++) s[c] *= inv;
    float a[5];
#pragma unroll
    for (int i = 0; i < 5; i++) {
        float t = mb1[i];
#pragma unroll
        for (int c = 0; c < 5; c++) t = fmaf(s[c], mw1[i * 5 + c], t);
        a[i] = fmaxf(t, 0.f);
    }
    float o0 = mb2[0], o1 = mb2[1];
#pragma unroll
    for (int i = 0; i < 5; i++) { o0 = fmaf(a[i], mw2[i], o0); o1 = fmaf(a[i], mw2[5 + i], o1); }
    float m2 = fmaxf(o0, o1);
    float e0 = __expf(o0 - m2), e1 = __expf(o1 - m2);
    float is = __fdividef(1.f, e0 + e1);
    out_m[b * 2 + 0] = e0 * is;
    out_m[b * 2 + 1] = e1 * is;
}

// ---------------- host ----------------
extern "C" void kernel_launch(void* const* d_in, const int* in_sizes, int n_in,
                              void* d_out, int out_size)
{
    const float* x     = (const float*)d_in[0];
    const float* w_ih0 = (const float*)d_in[1];
    const float* w_hh0 = (const float*)d_in[2];
    const float* b_ih0 = (const float*)d_in[3];
    const float* b_hh0 = (const float*)d_in[4];
    const float* w_ih1 = (const float*)d_in[5];
    const float* w_hh1 = (const float*)d_in[6];
    const float* b_ih1 = (const float*)d_in[7];
    const float* b_hh1 = (const float*)d_in[8];
    const float* w_ih2 = (const float*)d_in[9];
    const float* w_hh2 = (const float*)d_in[10];
    const float* b_ih2 = (const float*)d_in[11];
    const float* b_hh2 = (const float*)d_in[12];
    const float* fw1   = (const float*)d_in[13];
    const float* fb1   = (const float*)d_in[14];
    const float* fw2   = (const float*)d_in[15];
    const float* fb2   = (const float*)d_in[16];
    const float* fw3   = (const float*)d_in[17];
    const float* fb3   = (const float*)d_in[18];
    const float* mw1   = (const float*)d_in[19];
    const float* mb1   = (const float*)d_in[20];
    const float* mw2   = (const float*)d_in[21];
    const float* mb2   = (const float*)d_in[22];
    float* out = (float*)d_out;

    const int SM0 = 64  * (132 + 194) * 4;   // 83456 B
    const int SM1 = 120 * (132 + 194) * 4;   // 156480 B
    const int SMH = (128*124 + 60*120 + 128*68 + 40*60 + 128*44 + 5*40) * 4; // 160032 B

    cudaFuncSetAttribute(proj_kernel<64, true>,   cudaFuncAttributeMaxDynamicSharedMemorySize, SM0);
    cudaFuncSetAttribute(proj_kernel<120, false>, cudaFuncAttributeMaxDynamicSharedMemorySize, SM1);
    cudaFuncSetAttribute(head_kernel,             cudaFuncAttributeMaxDynamicSharedMemorySize, SMH);

    dim3 pg(T_LEN / 128, NB, 2);

    proj_kernel<64, true><<<pg, 512, SM0>>>(x, w_ih0, b_ih0);
    scan_kernel<<<NB, 256>>>(w_hh0, b_hh0);

    proj_kernel<120, false><<<pg, 512, SM1>>>(nullptr, w_ih1, b_ih1);
    scan_kernel<<<NB, 256>>>(w_hh1, b_hh1);

    proj_kernel<120, false><<<pg, 512, SM1>>>(nullptr, w_ih2, b_ih2);
    scan_kernel<<<NB, 256>>>(w_hh2, b_hh2);

    head_kernel<<<T_LEN, 512, SMH>>>(fw1, fb1, fw2, fb2, fw3, fb3);
    softmax_kernel<<<NB * 5, 256>>>(out);
    m_kernel<<<1, 128>>>(mw1, mb1, mw2, mb2, out + (size_t)NB * 5 * T_LEN);
}